// round 6
// baseline (speedup 1.0000x reference)
#include <cuda_runtime.h>
#include <math.h>

#define T_STEPS 4
#define ROWS    8192      // B*N = 8*1024
#define DDIM    512
#define FDIM    2048
#define MTOT    (T_STEPS*ROWS)   // 32768

typedef unsigned long long u64;

// Scratch (device globals -- no runtime allocation allowed)
__device__ float g_h[(size_t)T_STEPS * ROWS * FDIM];  // 256 MiB: hidden acts / spikes
__device__ float g_y[(size_t)T_STEPS * ROWS * DDIM];  //  64 MiB: layer-2 preacts

// ---- packed f32x2 helpers (sm_100+: fma.rn.f32x2; ptxas never emits it) ----
__device__ __forceinline__ u64 pack2(float lo, float hi) {
    u64 r; asm("mov.b64 %0, {%1, %2};" : "=l"(r) : "f"(lo), "f"(hi)); return r;
}
__device__ __forceinline__ void unpack2(u64 v, float& lo, float& hi) {
    asm("mov.b64 {%0, %1}, %2;" : "=f"(lo), "=f"(hi) : "l"(v));
}
#define FFMA2(d, a, b) \
    asm("fma.rn.f32x2 %0, %1, %2, %0;" : "+l"(d) : "l"(a), "l"(b))

// ---------------------------------------------------------------------------
// 128x128x16 fp32 SGEMM with fused bias, packed-f32x2 inner loop.
// C[M,N] = A[M,K]*B[K,N] + bias. 256 threads, 8x8 per thread (8x4 f32x2).
// A staged in smem as PRE-DUPLICATED u64 pairs (a,a): no per-k mov.b64 packs,
// a-frags via LDS.128. Inner loop ordered j-outer/i-inner so 8 consecutive
// FFMA2s share the b operand slot (operand-reuse-cache friendly -> rt 2).
// Per-output accumulation order identical to scalar/R2 version (k strictly
// sequential, same lane pairing) -> bit-identical results.
// ---------------------------------------------------------------------------
__global__ __launch_bounds__(256, 2)
void sgemm_bias_128(const float* __restrict__ A, const float* __restrict__ B,
                    const float* __restrict__ bias, float* __restrict__ C,
                    int M, int N, int K) {
    const int BK = 16;
    __shared__ u64   As2[16][128];   // duplicated (a,a) pairs, [k][m]
    __shared__ float Bs[16][128];

    const int tid = threadIdx.x;
    const int bm  = blockIdx.y * 128;
    const int bn  = blockIdx.x * 128;
    const int tr  = (tid >> 4) * 8;   // 0..120
    const int tc  = (tid & 15) * 8;   // 0..120

    u64 acc[8][4];
#pragma unroll
    for (int i = 0; i < 8; i++)
#pragma unroll
        for (int j = 0; j < 4; j++) acc[i][j] = 0ull;

    const float* Aptr = A + (size_t)bm * K;
    const float* Bptr = B + bn;

    for (int kt = 0; kt < K; kt += BK) {
        // Load A tile 128x16 (512 float4), store transposed as duplicated pairs
#pragma unroll
        for (int i = 0; i < 2; i++) {
            int id = tid + i * 256;
            int r  = id >> 2;
            int c4 = (id & 3) << 2;
            float4 v = *(const float4*)(Aptr + (size_t)r * K + kt + c4);
            As2[c4 + 0][r] = pack2(v.x, v.x);
            As2[c4 + 1][r] = pack2(v.y, v.y);
            As2[c4 + 2][r] = pack2(v.z, v.z);
            As2[c4 + 3][r] = pack2(v.w, v.w);
        }
        // Load B tile 16x128 (512 float4), direct
#pragma unroll
        for (int i = 0; i < 2; i++) {
            int id = tid + i * 256;
            int r  = id >> 5;
            int c  = (id & 31) << 2;
            *(float4*)&Bs[r][c] = *(const float4*)(Bptr + (size_t)(kt + r) * N + c);
        }
        __syncthreads();

#pragma unroll
        for (int k = 0; k < BK; k++) {
            // A fragment: 8 duplicated pairs via 4x LDS.128 (broadcast addrs)
            ulonglong2 a01 = *(const ulonglong2*)&As2[k][tr + 0];
            ulonglong2 a23 = *(const ulonglong2*)&As2[k][tr + 2];
            ulonglong2 a45 = *(const ulonglong2*)&As2[k][tr + 4];
            ulonglong2 a67 = *(const ulonglong2*)&As2[k][tr + 6];
            u64 a2[8] = {a01.x, a01.y, a23.x, a23.y, a45.x, a45.y, a67.x, a67.y};
            // B fragment: 4 packed pairs
            const ulonglong2* bp = (const ulonglong2*)&Bs[k][tc];
            ulonglong2 bv0 = bp[0];
            ulonglong2 bv1 = bp[1];
            u64 b2[4] = {bv0.x, bv0.y, bv1.x, bv1.y};

            // j-outer / i-inner: 8 consecutive FFMA2 share b2[j] (reuse slot)
#pragma unroll
            for (int j = 0; j < 4; j++)
#pragma unroll
                for (int i = 0; i < 8; i++)
                    FFMA2(acc[i][j], a2[i], b2[j]);
        }
        __syncthreads();
    }

#pragma unroll
    for (int i = 0; i < 8; i++) {
        float* Crow = C + (size_t)(bm + tr + i) * N + bn + tc;
#pragma unroll
        for (int j = 0; j < 4; j++) {
            float lo, hi;
            unpack2(acc[i][j], lo, hi);
            Crow[2 * j + 0] = lo + bias[bn + tc + 2 * j + 0];
            Crow[2 * j + 1] = hi + bias[bn + tc + 2 * j + 1];
        }
    }
}

// ---------------------------------------------------------------------------
// Block-wide sum reduction
// ---------------------------------------------------------------------------
template <int NT>
__device__ __forceinline__ float block_sum(float val, float* sh) {
    const int lane = threadIdx.x & 31;
    const int warp = threadIdx.x >> 5;
#pragma unroll
    for (int o = 16; o > 0; o >>= 1) val += __shfl_down_sync(0xffffffffu, val, o);
    if (lane == 0) sh[warp] = val;
    __syncthreads();
    const int NW = NT / 32;
    if (warp == 0) {
        float v = (lane < NW) ? sh[lane] : 0.0f;
#pragma unroll
        for (int o = 16; o > 0; o >>= 1) v += __shfl_down_sync(0xffffffffu, v, o);
        if (lane == 0) sh[0] = v;
    }
    __syncthreads();
    float r = sh[0];
    __syncthreads();
    return r;
}

// ---------------------------------------------------------------------------
// Fused LayerNorm (per row, per t) + LIF scan across T (in registers).
// ---------------------------------------------------------------------------
template <int FD, int NT>
__global__ void ln_lif_kernel(const float* __restrict__ in,
                              const float* __restrict__ w,
                              const float* __restrict__ bvec,
                              const float* __restrict__ betap,
                              float* __restrict__ out) {
    const int VPT = FD / NT;
    const int r   = blockIdx.x;
    const int tid = threadIdx.x;
    __shared__ float sh[32];

    float v[T_STEPS][VPT];
    float wv[VPT], bv[VPT];
#pragma unroll
    for (int j = 0; j < VPT; j++) {
        wv[j] = w[tid + j * NT];
        bv[j] = bvec[tid + j * NT];
    }
#pragma unroll
    for (int t = 0; t < T_STEPS; t++) {
        const float* rowp = in + ((size_t)t * ROWS + r) * FD;
#pragma unroll
        for (int j = 0; j < VPT; j++) v[t][j] = rowp[tid + j * NT];
    }

#pragma unroll
    for (int t = 0; t < T_STEPS; t++) {
        float s = 0.0f;
#pragma unroll
        for (int j = 0; j < VPT; j++) s += v[t][j];
        s = block_sum<NT>(s, sh);
        const float mu = s * (1.0f / FD);

        float q = 0.0f;
#pragma unroll
        for (int j = 0; j < VPT; j++) {
            float d = v[t][j] - mu;
            q += d * d;
        }
        q = block_sum<NT>(q, sh);
        const float inv = 1.0f / sqrtf(q * (1.0f / FD) + 1e-5f);

#pragma unroll
        for (int j = 0; j < VPT; j++)
            v[t][j] = (v[t][j] - mu) * inv * wv[j] + bv[j];
    }

    // LIF scan across T in registers (soft reset, threshold 1.0)
    const float beta = *betap;
#pragma unroll
    for (int j = 0; j < VPT; j++) {
        float mem = 0.0f;
#pragma unroll
        for (int t = 0; t < T_STEPS; t++) {
            mem = fmaf(beta, mem, v[t][j]);
            float spk = (mem - 1.0f) > 0.0f ? 1.0f : 0.0f;
            mem -= spk;
            v[t][j] = spk;
        }
    }

#pragma unroll
    for (int t = 0; t < T_STEPS; t++) {
        float* rowp = out + ((size_t)t * ROWS + r) * FD;
#pragma unroll
        for (int j = 0; j < VPT; j++) rowp[tid + j * NT] = v[t][j];
    }
}

// ---------------------------------------------------------------------------
extern "C" void kernel_launch(void* const* d_in, const int* in_sizes, int n_in,
                              void* d_out, int out_size) {
    const float* x     = (const float*)d_in[0];
    const float* W1    = (const float*)d_in[1];
    const float* b1    = (const float*)d_in[2];
    const float* ln1w  = (const float*)d_in[3];
    const float* ln1b  = (const float*)d_in[4];
    const float* beta1 = (const float*)d_in[5];
    const float* W2    = (const float*)d_in[6];
    const float* b2    = (const float*)d_in[7];
    const float* ln2w  = (const float*)d_in[8];
    const float* ln2b  = (const float*)d_in[9];
    const float* beta2 = (const float*)d_in[10];
    float* out = (float*)d_out;

    float *h, *y;
    cudaGetSymbolAddress((void**)&h, g_h);
    cudaGetSymbolAddress((void**)&y, g_y);

    // GEMM1: [32768,512] x [512,2048] + b1 -> h
    {
        dim3 grid(FDIM / 128, MTOT / 128);
        sgemm_bias_128<<<grid, 256>>>(x, W1, b1, h, MTOT, FDIM, DDIM);
    }
    // LN1 + LIF1 (in place: h preacts -> h spikes)
    ln_lif_kernel<FDIM, 256><<<ROWS, 256>>>(h, ln1w, ln1b, beta1, h);

    // GEMM2: [32768,2048] x [2048,512] + b2 -> y
    {
        dim3 grid(DDIM / 128, MTOT / 128);
        sgemm_bias_128<<<grid, 256>>>(h, W2, b2, y, MTOT, DDIM, FDIM);
    }
    // LN2 + LIF2 -> d_out
    ln_lif_kernel<DDIM, 128><<<ROWS, 128>>>(y, ln2w, ln2b, beta2, out);
}

// round 7
// speedup vs baseline: 1.0540x; 1.0540x over previous
#include <cuda_runtime.h>
#include <math.h>

#define T_STEPS 4
#define ROWS    8192      // B*N = 8*1024
#define DDIM    512
#define FDIM    2048
#define MTOT    (T_STEPS*ROWS)   // 32768

typedef unsigned int u32;
typedef unsigned long long u64;

// Scratch (device globals -- no runtime allocation allowed)
__device__ float g_h[(size_t)MTOT * FDIM];        // 256 MiB: layer-1 preacts
__device__ float g_y[(size_t)MTOT * DDIM];        //  64 MiB: layer-2 preacts
__device__ u32   g_mask[(size_t)MTOT * (FDIM/32)];//   8 MiB: spike bitmask

// ---- packed f32x2 helpers ----
__device__ __forceinline__ u64 pack2(float lo, float hi) {
    u64 r; asm("mov.b64 %0, {%1, %2};" : "=l"(r) : "f"(lo), "f"(hi)); return r;
}
__device__ __forceinline__ void unpack2(u64 v, float& lo, float& hi) {
    asm("mov.b64 {%0, %1}, %2;" : "=f"(lo), "=f"(hi) : "l"(v));
}
#define FFMA2(d, a, b) \
    asm("fma.rn.f32x2 %0, %1, %2, %0;" : "+l"(d) : "l"(a), "l"(b))
#define FADD2(d, s) \
    asm("add.rn.f32x2 %0, %0, %1;" : "+l"(d) : "l"(s))

__device__ __forceinline__ u32 smem_u32(const void* p) {
    u32 a;
    asm("{ .reg .u64 t; cvta.to.shared.u64 t, %1; cvt.u32.u64 %0, t; }" : "=r"(a) : "l"(p));
    return a;
}
__device__ __forceinline__ void cp16(u32 dst, const void* src) {
    asm volatile("cp.async.cg.shared.global [%0], [%1], 16;" :: "r"(dst), "l"(src));
}
#define CP_COMMIT() asm volatile("cp.async.commit_group;" ::: "memory")
#define CP_WAIT(n)  asm volatile("cp.async.wait_group %0;" :: "n"(n) : "memory")

// ---------------------------------------------------------------------------
// GEMM1: R2's 128x128x16 fp32 SGEMM + bias, packed-f32x2 inner loop.
// Per-output accumulation k-sequential -> matches reference trajectory.
// ---------------------------------------------------------------------------
__global__ __launch_bounds__(256, 2)
void sgemm_bias_128(const float* __restrict__ A, const float* __restrict__ B,
                    const float* __restrict__ bias, float* __restrict__ C,
                    int M, int N, int K) {
    const int BK = 16;
    __shared__ float As[16][128];
    __shared__ float Bs[16][128];

    const int tid = threadIdx.x;
    const int bm  = blockIdx.y * 128;
    const int bn  = blockIdx.x * 128;
    const int tr  = (tid >> 4) * 8;
    const int tc  = (tid & 15) * 8;

    u64 acc[8][4];
#pragma unroll
    for (int i = 0; i < 8; i++)
#pragma unroll
        for (int j = 0; j < 4; j++) acc[i][j] = 0ull;

    const float* Aptr = A + (size_t)bm * K;
    const float* Bptr = B + bn;

    for (int kt = 0; kt < K; kt += BK) {
#pragma unroll
        for (int i = 0; i < 2; i++) {
            int id = tid + i * 256;
            int r  = id >> 2;
            int c4 = (id & 3) << 2;
            float4 v = *(const float4*)(Aptr + (size_t)r * K + kt + c4);
            As[c4 + 0][r] = v.x;
            As[c4 + 1][r] = v.y;
            As[c4 + 2][r] = v.z;
            As[c4 + 3][r] = v.w;
        }
#pragma unroll
        for (int i = 0; i < 2; i++) {
            int id = tid + i * 256;
            int r  = id >> 5;
            int c  = (id & 31) << 2;
            *(float4*)&Bs[r][c] = *(const float4*)(Bptr + (size_t)(kt + r) * N + c);
        }
        __syncthreads();

#pragma unroll
        for (int k = 0; k < BK; k++) {
            float4 av0 = *(const float4*)&As[k][tr];
            float4 av1 = *(const float4*)&As[k][tr + 4];
            u64 a2[8];
            a2[0] = pack2(av0.x, av0.x);
            a2[1] = pack2(av0.y, av0.y);
            a2[2] = pack2(av0.z, av0.z);
            a2[3] = pack2(av0.w, av0.w);
            a2[4] = pack2(av1.x, av1.x);
            a2[5] = pack2(av1.y, av1.y);
            a2[6] = pack2(av1.z, av1.z);
            a2[7] = pack2(av1.w, av1.w);
            const ulonglong2* bp = (const ulonglong2*)&Bs[k][tc];
            ulonglong2 bv0 = bp[0];
            ulonglong2 bv1 = bp[1];
            u64 b2[4] = {bv0.x, bv0.y, bv1.x, bv1.y};

#pragma unroll
            for (int i = 0; i < 8; i++)
#pragma unroll
                for (int j = 0; j < 4; j++)
                    FFMA2(acc[i][j], a2[i], b2[j]);
        }
        __syncthreads();
    }

#pragma unroll
    for (int i = 0; i < 8; i++) {
        float* Crow = C + (size_t)(bm + tr + i) * N + bn + tc;
#pragma unroll
        for (int j = 0; j < 4; j++) {
            float lo, hi;
            unpack2(acc[i][j], lo, hi);
            Crow[2 * j + 0] = lo + bias[bn + tc + 2 * j + 0];
            Crow[2 * j + 1] = hi + bias[bn + tc + 2 * j + 1];
        }
    }
}

// ---------------------------------------------------------------------------
// GEMM2 (sparse-exact): Y[m,:] = b2 + sum_{k: spike(m,k)} W2[k,:]
// Skipping spk==0 terms of the k-sequential fp32 sum is bit-exact, and
// fma(1,w,acc) == RN(acc+w), so this reproduces the dense GEMM2 bitwise.
// CTA: 64 rows x 512 cols. Warp: 8 rows (uniform mask byte per k, static
// unrolled row tests). Thread: 16 cols as 8 u64 f32x2 accumulators.
// W2 rows streamed via 3-deep cp.async ring, 8 k-rows per stage.
// ---------------------------------------------------------------------------
__global__ __launch_bounds__(256)
void spadd_gemm2(const u32* __restrict__ mask, const float* __restrict__ W2,
                 const float* __restrict__ bias, float* __restrict__ Y) {
    __shared__ float w2s[3][8][512];    // 48 KiB ring

    const int tid  = threadIdx.x;
    const int wid  = tid >> 5;
    const int lane = tid & 31;
    const int m0   = blockIdx.x * 64 + wid * 8;   // warp's 8 rows
    const int c0   = lane * 16;                   // thread's 16 cols

    u64 acc2[8][8];
#pragma unroll
    for (int r = 0; r < 8; r++)
#pragma unroll
        for (int q = 0; q < 8; q++) acc2[r][q] = 0ull;

    const u32 sbase = smem_u32(&w2s[0][0][0]);

    // issue chunk c (W2 rows [8c, 8c+8)) into ring slot c%3
    auto issue = [&](int c) {
        const char* src = (const char*)(W2 + (size_t)c * 8 * 512);
        const u32 dst = sbase + (u32)(c % 3) * 16384;
#pragma unroll
        for (int i = 0; i < 4; i++) {
            int off = (i * 256 + tid) * 16;
            cp16(dst + off, src + off);
        }
        CP_COMMIT();
    };

    issue(0);
    issue(1);

    u32 mrow[8];
    u32 anyb = 0;

    for (int ci = 0; ci < 256; ci++) {
        CP_WAIT(1);
        __syncthreads();
        if (ci + 2 < 256) issue(ci + 2);

        const int kb = ci * 8;
        if ((kb & 31) == 0) {           // refresh mask words every 32 k
            const int wi = kb >> 5;
            anyb = 0;
#pragma unroll
            for (int r = 0; r < 8; r++) {
                mrow[r] = mask[(size_t)(m0 + r) * (FDIM / 32) + wi];
                anyb |= mrow[r];
            }
        }

        const float* wrow = &w2s[ci % 3][0][0];
#pragma unroll
        for (int kk = 0; kk < 8; kk++) {
            const int kb5 = (kb + kk) & 31;
            if (!((anyb >> kb5) & 1)) continue;     // no row active at this k

            const ulonglong2* wp = (const ulonglong2*)(wrow + kk * 512 + c0);
            ulonglong2 w01 = wp[0];
            ulonglong2 w23 = wp[1];
            ulonglong2 w45 = wp[2];
            ulonglong2 w67 = wp[3];

#pragma unroll
            for (int r = 0; r < 8; r++) {
                if ((mrow[r] >> kb5) & 1) {
                    FADD2(acc2[r][0], w01.x);
                    FADD2(acc2[r][1], w01.y);
                    FADD2(acc2[r][2], w23.x);
                    FADD2(acc2[r][3], w23.y);
                    FADD2(acc2[r][4], w45.x);
                    FADD2(acc2[r][5], w45.y);
                    FADD2(acc2[r][6], w67.x);
                    FADD2(acc2[r][7], w67.y);
                }
            }
        }
    }

    // epilogue: + bias
    float bx[16];
#pragma unroll
    for (int q = 0; q < 4; q++) {
        float4 b4 = *(const float4*)(bias + c0 + q * 4);
        bx[q * 4 + 0] = b4.x; bx[q * 4 + 1] = b4.y;
        bx[q * 4 + 2] = b4.z; bx[q * 4 + 3] = b4.w;
    }
#pragma unroll
    for (int r = 0; r < 8; r++) {
        float* yr = Y + (size_t)(m0 + r) * DDIM + c0;
#pragma unroll
        for (int q = 0; q < 4; q++) {
            float lo0, hi0, lo1, hi1;
            unpack2(acc2[r][2 * q + 0], lo0, hi0);
            unpack2(acc2[r][2 * q + 1], lo1, hi1);
            float4 o;
            o.x = lo0 + bx[q * 4 + 0];
            o.y = hi0 + bx[q * 4 + 1];
            o.z = lo1 + bx[q * 4 + 2];
            o.w = hi1 + bx[q * 4 + 3];
            *(float4*)(yr + q * 4) = o;
        }
    }
}

// ---------------------------------------------------------------------------
// Block-wide sum reduction
// ---------------------------------------------------------------------------
template <int NT>
__device__ __forceinline__ float block_sum(float val, float* sh) {
    const int lane = threadIdx.x & 31;
    const int warp = threadIdx.x >> 5;
#pragma unroll
    for (int o = 16; o > 0; o >>= 1) val += __shfl_down_sync(0xffffffffu, val, o);
    if (lane == 0) sh[warp] = val;
    __syncthreads();
    const int NW = NT / 32;
    if (warp == 0) {
        float v = (lane < NW) ? sh[lane] : 0.0f;
#pragma unroll
        for (int o = 16; o > 0; o >>= 1) v += __shfl_down_sync(0xffffffffu, v, o);
        if (lane == 0) sh[0] = v;
    }
    __syncthreads();
    float r = sh[0];
    __syncthreads();
    return r;
}

// ---------------------------------------------------------------------------
// Fused LayerNorm + LIF scan. MASK_OUT: emit spike bitmask (layer 1);
// otherwise emit dense float spikes (layer 2 -> d_out).
// ---------------------------------------------------------------------------
template <int FD, int NT, bool MASK_OUT>
__global__ void ln_lif_kernel(const float* __restrict__ in,
                              const float* __restrict__ w,
                              const float* __restrict__ bvec,
                              const float* __restrict__ betap,
                              float* __restrict__ out,
                              u32* __restrict__ maskout) {
    const int VPT = FD / NT;
    const int r   = blockIdx.x;
    const int tid = threadIdx.x;
    const int lane = tid & 31, wid = tid >> 5;
    __shared__ float sh[32];

    float v[T_STEPS][VPT];
    float wv[VPT], bv[VPT];
#pragma unroll
    for (int j = 0; j < VPT; j++) {
        wv[j] = w[tid + j * NT];
        bv[j] = bvec[tid + j * NT];
    }
#pragma unroll
    for (int t = 0; t < T_STEPS; t++) {
        const float* rowp = in + ((size_t)t * ROWS + r) * FD;
#pragma unroll
        for (int j = 0; j < VPT; j++) v[t][j] = rowp[tid + j * NT];
    }

#pragma unroll
    for (int t = 0; t < T_STEPS; t++) {
        float s = 0.0f;
#pragma unroll
        for (int j = 0; j < VPT; j++) s += v[t][j];
        s = block_sum<NT>(s, sh);
        const float mu = s * (1.0f / FD);

        float q = 0.0f;
#pragma unroll
        for (int j = 0; j < VPT; j++) {
            float d = v[t][j] - mu;
            q += d * d;
        }
        q = block_sum<NT>(q, sh);
        const float inv = 1.0f / sqrtf(q * (1.0f / FD) + 1e-5f);

#pragma unroll
        for (int j = 0; j < VPT; j++)
            v[t][j] = (v[t][j] - mu) * inv * wv[j] + bv[j];
    }

    const float beta = *betap;
#pragma unroll
    for (int j = 0; j < VPT; j++) {
        float mem = 0.0f;
#pragma unroll
        for (int t = 0; t < T_STEPS; t++) {
            mem = fmaf(beta, mem, v[t][j]);
            float spk = (mem - 1.0f) > 0.0f ? 1.0f : 0.0f;
            mem -= spk;
            v[t][j] = spk;
        }
    }

#pragma unroll
    for (int t = 0; t < T_STEPS; t++) {
        if (MASK_OUT) {
#pragma unroll
            for (int j = 0; j < VPT; j++) {
                u32 bits = __ballot_sync(0xffffffffu, v[t][j] != 0.0f);
                if (lane == 0)
                    maskout[(size_t)(t * ROWS + r) * (FD / 32) + j * (NT / 32) + wid] = bits;
            }
        } else {
            float* rowp = out + ((size_t)t * ROWS + r) * FD;
#pragma unroll
            for (int j = 0; j < VPT; j++) rowp[tid + j * NT] = v[t][j];
        }
    }
}

// ---------------------------------------------------------------------------
extern "C" void kernel_launch(void* const* d_in, const int* in_sizes, int n_in,
                              void* d_out, int out_size) {
    const float* x     = (const float*)d_in[0];
    const float* W1    = (const float*)d_in[1];
    const float* b1    = (const float*)d_in[2];
    const float* ln1w  = (const float*)d_in[3];
    const float* ln1b  = (const float*)d_in[4];
    const float* beta1 = (const float*)d_in[5];
    const float* W2    = (const float*)d_in[6];
    const float* b2    = (const float*)d_in[7];
    const float* ln2w  = (const float*)d_in[8];
    const float* ln2b  = (const float*)d_in[9];
    const float* beta2 = (const float*)d_in[10];
    float* out = (float*)d_out;

    float *h, *y;
    u32* msk;
    cudaGetSymbolAddress((void**)&h, g_h);
    cudaGetSymbolAddress((void**)&y, g_y);
    cudaGetSymbolAddress((void**)&msk, g_mask);

    // GEMM1: [32768,512] x [512,2048] + b1 -> h
    {
        dim3 grid(FDIM / 128, MTOT / 128);
        sgemm_bias_128<<<grid, 256>>>(x, W1, b1, h, MTOT, FDIM, DDIM);
    }
    // LN1 + LIF1 -> spike bitmask only
    ln_lif_kernel<FDIM, 256, true><<<ROWS, 256>>>(h, ln1w, ln1b, beta1, nullptr, msk);

    // GEMM2 (sparse-exact): mask x W2 + b2 -> y
    spadd_gemm2<<<MTOT / 64, 256>>>(msk, W2, b2, y);

    // LN2 + LIF2 -> d_out
    ln_lif_kernel<DDIM, 128, false><<<ROWS, 128>>>(y, ln2w, ln2b, beta2, out, nullptr);
}